// round 2
// baseline (speedup 1.0000x reference)
#include <cuda_runtime.h>

// YOLO loss: p, a are [N, 7, 7, 30] f32. Channels 0..9 are NEVER used by the
// reference (cls loss = channels 10..29, boxes = 20..29), so we only load
// bytes [40,120) of each 120-byte record.
//
// Kernel 1: each 256-thread block stages 256 records' channels 10..29 into
// shared memory with coalesced float2 loads, computes the per-cell loss,
// block-reduces, writes one partial per block.
// Kernel 2: deterministic single-block reduction of partials -> d_out[0].

#define EPS_F 1e-6f
#define CELLS_PER_BLOCK 256
#define SMEM_STRIDE 21   // 20 channels + 1 pad; gcd(21,32)=1 -> conflict-free

__device__ float g_partials[8192];

__device__ __forceinline__ float signf(float x) {
    return (x > 0.f) ? 1.f : ((x < 0.f) ? -1.f : 0.f);
}

__device__ __forceinline__ float iou_pair(
    float px, float py, float pw, float ph,
    float ax, float ay, float aw, float ah)
{
    float p_tlx = px - pw * 0.5f, p_tly = py - ph * 0.5f;
    float p_brx = px + pw * 0.5f, p_bry = py + ph * 0.5f;
    float a_tlx = ax - aw * 0.5f, a_tly = ay - ah * 0.5f;
    float a_brx = ax + aw * 0.5f, a_bry = ay + ah * 0.5f;
    float sx = fminf(p_brx, a_brx) - fmaxf(p_tlx, a_tlx);
    float sy = fminf(p_bry, a_bry) - fmaxf(p_tly, a_tly);
    sx = fmaxf(sx, 0.f);
    sy = fmaxf(sy, 0.f);
    float inter = sx * sy;
    float uni = pw * ph + aw * ah - inter;
    // reference: where(u==0, 0, inter) / where(u==0, EPS, u)
    if (uni == 0.f) return 0.f;
    return inter / uni;
}

__global__ __launch_bounds__(CELLS_PER_BLOCK)
void yolo_loss_partial(const float* __restrict__ p,
                       const float* __restrict__ a,
                       int ncells)
{
    __shared__ float sp[CELLS_PER_BLOCK * SMEM_STRIDE];
    __shared__ float sa[CELLS_PER_BLOCK * SMEM_STRIDE];

    const int tid = threadIdx.x;
    const int blockStart = blockIdx.x * CELLS_PER_BLOCK;
    const int nrec = min(CELLS_PER_BLOCK, ncells - blockStart);

    // Coalesced staging: each record contributes 10 float2 (channels 10..29,
    // byte offset 40 within the 120-byte record; 40 is 8B-aligned).
    const float2* p2 = reinterpret_cast<const float2*>(p);
    const float2* a2 = reinterpret_cast<const float2*>(a);
    const int total = nrec * 10;
    for (int i = tid; i < total; i += CELLS_PER_BLOCK) {
        int rec = i / 10;
        int j = i - rec * 10;
        long g = (long)(blockStart + rec) * 15 + 5 + j;  // 120B = 15 float2; +40B = 5
        float2 vp = __ldg(&p2[g]);
        float2 va = __ldg(&a2[g]);
        int d = rec * SMEM_STRIDE + 2 * j;
        sp[d] = vp.x; sp[d + 1] = vp.y;
        sa[d] = va.x; sa[d + 1] = va.y;
    }
    __syncthreads();

    float loss = 0.f;
    if (tid < nrec) {
        const float* cp = &sp[tid * SMEM_STRIDE];  // k = channel - 10, k in [0,20)
        const float* ca = &sa[tid * SMEM_STRIDE];

        // boxes: channel 20+5b+i -> k = 10+5b+i
        float px[2], py[2], pw[2], ph[2], pc[2];
        float qx[2], qy[2], qw[2], qh[2], qc[2];
        #pragma unroll
        for (int b = 0; b < 2; b++) {
            int o = 10 + 5 * b;
            px[b] = cp[o]; py[b] = cp[o + 1]; pw[b] = cp[o + 2];
            ph[b] = cp[o + 3]; pc[b] = cp[o + 4];
            qx[b] = ca[o]; qy[b] = ca[o + 1]; qw[b] = ca[o + 2];
            qh[b] = ca[o + 3]; qc[b] = ca[o + 4];
        }

        float maxiou[2];
        #pragma unroll
        for (int i = 0; i < 2; i++) {
            float i0 = iou_pair(px[i], py[i], pw[i], ph[i], qx[0], qy[0], qw[0], qh[0]);
            float i1 = iou_pair(px[i], py[i], pw[i], ph[i], qx[1], qy[1], qw[1], qh[1]);
            maxiou[i] = fmaxf(i0, i1);
        }

        bool obj = qc[0] > 0.f;                 // a attr4, box 0 (channel 24)
        bool resp0 = maxiou[0] >= maxiou[1];     // argmax first-tie -> index 0
        float ob[2];
        ob[0] = (obj && resp0)  ? 1.f : 0.f;
        ob[1] = (obj && !resp0) ? 1.f : 0.f;

        float coord = 0.f, cobj = 0.f, cnoobj = 0.f;
        #pragma unroll
        for (int b = 0; b < 2; b++) {
            float o = ob[b];
            float no = 1.f - o;
            float dx = o * qx[b] - o * px[b];
            float dy = o * qy[b] - o * py[b];
            coord += dx * dx + dy * dy;
            float sqa = signf(qw[b]) * sqrtf(qw[b] + EPS_F);
            float sqp = signf(pw[b]) * sqrtf(pw[b] + EPS_F);
            float dw = o * sqa - o * sqp;
            float sha = signf(qh[b]) * sqrtf(qh[b] + EPS_F);
            float shp = signf(ph[b]) * sqrtf(ph[b] + EPS_F);
            float dh = o * sha - o * shp;
            coord += dw * dw + dh * dh;
            float t1 = o * o - o * pc[b];
            cobj += t1 * t1;
            float t2 = no * o - no * pc[b];
            cnoobj += t2 * t2;
        }

        float cls = 0.f;
        if (obj) {
            #pragma unroll
            for (int k = 0; k < 20; k++) {
                float d = cp[k] - ca[k];
                cls += d * d;
            }
        }

        loss = 5.0f * coord + cobj + 0.5f * cnoobj + cls;
    }

    // block reduction
    #pragma unroll
    for (int off = 16; off > 0; off >>= 1)
        loss += __shfl_down_sync(0xFFFFFFFFu, loss, off);

    __shared__ float warpsum[8];
    if ((tid & 31) == 0) warpsum[tid >> 5] = loss;
    __syncthreads();
    if (tid < 8) {
        float v = warpsum[tid];
        #pragma unroll
        for (int off = 4; off > 0; off >>= 1)
            v += __shfl_down_sync(0xFFu, v, off);
        if (tid == 0) g_partials[blockIdx.x] = v;
    }
}

__global__ __launch_bounds__(1024)
void yolo_loss_finalize(float* __restrict__ out, int nblocks)
{
    float s = 0.f;
    for (int i = threadIdx.x; i < nblocks; i += 1024)
        s += g_partials[i];

    #pragma unroll
    for (int off = 16; off > 0; off >>= 1)
        s += __shfl_down_sync(0xFFFFFFFFu, s, off);

    __shared__ float warpsum[32];
    if ((threadIdx.x & 31) == 0) warpsum[threadIdx.x >> 5] = s;
    __syncthreads();
    if (threadIdx.x < 32) {
        float v = warpsum[threadIdx.x];
        #pragma unroll
        for (int off = 16; off > 0; off >>= 1)
            v += __shfl_down_sync(0xFFFFFFFFu, v, off);
        if (threadIdx.x == 0) out[0] = v;
    }
}

extern "C" void kernel_launch(void* const* d_in, const int* in_sizes, int n_in,
                              void* d_out, int out_size)
{
    const float* p = (const float*)d_in[0];
    const float* a = (const float*)d_in[1];
    int ncells = in_sizes[0] / 30;                    // N*S*S = 802816
    int nblocks = (ncells + CELLS_PER_BLOCK - 1) / CELLS_PER_BLOCK;  // 3136

    yolo_loss_partial<<<nblocks, CELLS_PER_BLOCK>>>(p, a, ncells);
    yolo_loss_finalize<<<1, 1024>>>((float*)d_out, nblocks);
}

// round 3
// speedup vs baseline: 1.0423x; 1.0423x over previous
#include <cuda_runtime.h>

// YOLO loss, single fused kernel.
// p, a: [N,7,7,30] f32. Channels 0..9 are never read by the reference
// (cls loss = channels 10..29, box attrs = 20..29), so only bytes [40,120)
// of each 120-byte record are loaded (saves 2/15 of DRAM sectors).
//
// Per block: stage 128 records' channels 10..29 into smem with coalesced
// float2 loads, compute per-cell loss (IoU argmax via cross-multiplied
// fraction compares -- no divisions), block-reduce, write one partial.
// The last block to finish (atomic ticket) reduces all partials into out[0]
// in fixed index order (deterministic) and resets the ticket for graph replay.

#define EPS_F 1e-6f
#define CPB 128          // cells per block == threads per block
#define SMEM_STRIDE 21   // 20 channels + 1 pad; gcd(21,32)=1 -> conflict-free

__device__ float g_partials[8192];
__device__ unsigned int g_ticket;   // zero-initialized; reset by last block

__device__ __forceinline__ float signf(float x) {
    return (x > 0.f) ? 1.f : ((x < 0.f) ? -1.f : 0.f);
}

// sign(x) * sqrt(x + EPS), single-MUFU sqrt
__device__ __forceinline__ float ssqrt(float x) {
    float r;
    float xe = x + EPS_F;
    asm("sqrt.approx.f32 %0, %1;" : "=f"(r) : "f"(xe));
    return signf(x) * r;
}

// IoU as a fraction (n/d) with d > 0; matches reference's
// where(u==0, 0, inter) / where(u==0, EPS, u).
__device__ __forceinline__ void iou_frac(
    float px, float py, float pw, float ph,
    float ax, float ay, float aw, float ah,
    float& n, float& d)
{
    float sx = fminf(px + pw * 0.5f, ax + aw * 0.5f)
             - fmaxf(px - pw * 0.5f, ax - aw * 0.5f);
    float sy = fminf(py + ph * 0.5f, ay + ah * 0.5f)
             - fmaxf(py - ph * 0.5f, ay - ah * 0.5f);
    sx = fmaxf(sx, 0.f);
    sy = fmaxf(sy, 0.f);
    float inter = sx * sy;
    float uni = fmaf(pw, ph, fmaf(aw, ah, -inter));
    bool z = (uni == 0.f);
    n = z ? 0.f : inter;
    d = z ? EPS_F : uni;
}

__global__ __launch_bounds__(CPB)
void yolo_loss_fused(const float* __restrict__ p,
                     const float* __restrict__ a,
                     float* __restrict__ out,
                     int ncells, int nblocks)
{
    __shared__ float sp[CPB * SMEM_STRIDE];
    __shared__ float sa[CPB * SMEM_STRIDE];

    const int tid = threadIdx.x;
    const int blockStart = blockIdx.x * CPB;
    const int nrec = min(CPB, ncells - blockStart);

    // ---- coalesced staging of channels 10..29 (10 float2 per record) ----
    const float2* p2 = reinterpret_cast<const float2*>(p);
    const float2* a2 = reinterpret_cast<const float2*>(a);
    const int total = nrec * 10;
    for (int i = tid; i < total; i += CPB) {
        int rec = i / 10;
        int j = i - rec * 10;
        long g = (long)(blockStart + rec) * 15 + 5 + j;  // 120B = 15 float2
        float2 vp = __ldg(&p2[g]);
        float2 va = __ldg(&a2[g]);
        int d = rec * SMEM_STRIDE + 2 * j;
        sp[d] = vp.x; sp[d + 1] = vp.y;
        sa[d] = va.x; sa[d + 1] = va.y;
    }
    __syncthreads();

    // ---- per-cell loss ----
    float loss = 0.f;
    if (tid < nrec) {
        const float* cp = &sp[tid * SMEM_STRIDE];  // k = channel-10, k in [0,20)
        const float* ca = &sa[tid * SMEM_STRIDE];

        float px[2], py[2], pw[2], ph[2], pc[2];
        float qx[2], qy[2], qw[2], qh[2], qc[2];
        #pragma unroll
        for (int b = 0; b < 2; b++) {
            int o = 10 + 5 * b;   // channels 20+5b.. -> k offset
            px[b] = cp[o]; py[b] = cp[o + 1]; pw[b] = cp[o + 2];
            ph[b] = cp[o + 3]; pc[b] = cp[o + 4];
            qx[b] = ca[o]; qy[b] = ca[o + 1]; qw[b] = ca[o + 2];
            qh[b] = ca[o + 3]; qc[b] = ca[o + 4];
        }

        // max_iou per predicted box as a fraction; argmax by cross-multiply
        float N[2], D[2];
        #pragma unroll
        for (int i = 0; i < 2; i++) {
            float n0, d0, n1, d1;
            iou_frac(px[i], py[i], pw[i], ph[i], qx[0], qy[0], qw[0], qh[0], n0, d0);
            iou_frac(px[i], py[i], pw[i], ph[i], qx[1], qy[1], qw[1], qh[1], n1, d1);
            bool take0 = (n0 * d1 >= n1 * d0);   // all d > 0
            N[i] = take0 ? n0 : n1;
            D[i] = take0 ? d0 : d1;
        }

        bool obj = qc[0] > 0.f;                    // a attr4 box0 (channel 24)
        bool resp0 = (N[0] * D[1] >= N[1] * D[0]); // argmax first-tie -> 0
        float ob[2];
        ob[0] = (obj && resp0)  ? 1.f : 0.f;
        ob[1] = (obj && !resp0) ? 1.f : 0.f;

        float coord = 0.f, cobj = 0.f, cnoobj = 0.f;
        #pragma unroll
        for (int b = 0; b < 2; b++) {
            float o = ob[b];
            float no = 1.f - o;
            float dx = o * qx[b] - o * px[b];
            float dy = o * qy[b] - o * py[b];
            coord += dx * dx + dy * dy;
            float dw = o * ssqrt(qw[b]) - o * ssqrt(pw[b]);
            float dh = o * ssqrt(qh[b]) - o * ssqrt(ph[b]);
            coord += dw * dw + dh * dh;
            float t1 = o * o - o * pc[b];
            cobj += t1 * t1;
            float t2 = no * o - no * pc[b];
            cnoobj += t2 * t2;
        }

        float cls = 0.f;
        if (obj) {
            #pragma unroll
            for (int k = 0; k < 20; k++) {
                float d = cp[k] - ca[k];
                cls += d * d;
            }
        }

        loss = 5.0f * coord + cobj + 0.5f * cnoobj + cls;
    }

    // ---- block reduction (4 warps) ----
    #pragma unroll
    for (int off = 16; off > 0; off >>= 1)
        loss += __shfl_down_sync(0xFFFFFFFFu, loss, off);

    __shared__ float warpsum[4];
    if ((tid & 31) == 0) warpsum[tid >> 5] = loss;
    __syncthreads();

    __shared__ bool s_last;
    if (tid == 0) {
        float v = warpsum[0] + warpsum[1] + warpsum[2] + warpsum[3];
        g_partials[blockIdx.x] = v;
        __threadfence();
        unsigned int t = atomicAdd(&g_ticket, 1u);
        s_last = (t == (unsigned int)(nblocks - 1));
    }
    __syncthreads();

    // ---- last block: deterministic final reduction + ticket reset ----
    if (s_last) {
        __threadfence();  // make all partials visible
        float s = 0.f;
        for (int i = tid; i < nblocks; i += CPB)
            s += g_partials[i];
        #pragma unroll
        for (int off = 16; off > 0; off >>= 1)
            s += __shfl_down_sync(0xFFFFFFFFu, s, off);
        if ((tid & 31) == 0) warpsum[tid >> 5] = s;
        __syncthreads();
        if (tid == 0) {
            out[0] = warpsum[0] + warpsum[1] + warpsum[2] + warpsum[3];
            g_ticket = 0;   // reset for next graph replay
        }
    }
}

extern "C" void kernel_launch(void* const* d_in, const int* in_sizes, int n_in,
                              void* d_out, int out_size)
{
    const float* p = (const float*)d_in[0];
    const float* a = (const float*)d_in[1];
    int ncells = in_sizes[0] / 30;                 // 16384*49 = 802816
    int nblocks = (ncells + CPB - 1) / CPB;        // 6272

    yolo_loss_fused<<<nblocks, CPB>>>(p, a, (float*)d_out, ncells, nblocks);
}

// round 5
// speedup vs baseline: 1.0530x; 1.0102x over previous
#include <cuda_runtime.h>

// YOLO loss, single fused kernel.
// p, a: [N,7,7,30] f32. Channels 0..9 are never read by the reference
// (cls loss = channels 10..29, box attrs = 20..29), so only bytes [40,120)
// of each 120-byte record are loaded (saves 2/15 of DRAM sectors).
//
// Per block: stage 128 records' channels 10..29 into smem with coalesced
// float2 loads (fully unrolled fast path -> 20 LDG.64 batched per thread
// for deep MLP), compute per-cell loss (IoU argmax via cross-multiplied
// fraction compares -- no divisions), block-reduce, write one partial.
// The last block (atomic ticket) reduces all partials deterministically
// into out[0] and resets the ticket for graph replay.

#define EPS_F 1e-6f
#define CPB 128          // cells per block == threads per block
#define SMEM_STRIDE 21   // 20 channels + 1 pad; gcd(21,32)=1 -> conflict-free

__device__ float g_partials[8192];
__device__ unsigned int g_ticket;   // zero-initialized; reset by last block

__device__ __forceinline__ float signf(float x) {
    return (x > 0.f) ? 1.f : ((x < 0.f) ? -1.f : 0.f);
}

// sign(x) * sqrt(x + EPS), single-MUFU sqrt
__device__ __forceinline__ float ssqrt(float x) {
    float r;
    float xe = x + EPS_F;
    asm("sqrt.approx.f32 %0, %1;" : "=f"(r) : "f"(xe));
    return signf(x) * r;
}

// IoU as a fraction (n/d) with d > 0; matches reference's
// where(u==0, 0, inter) / where(u==0, EPS, u).
__device__ __forceinline__ void iou_frac(
    float px, float py, float pw, float ph,
    float ax, float ay, float aw, float ah,
    float& n, float& d)
{
    float sx = fminf(px + pw * 0.5f, ax + aw * 0.5f)
             - fmaxf(px - pw * 0.5f, ax - aw * 0.5f);
    float sy = fminf(py + ph * 0.5f, ay + ah * 0.5f)
             - fmaxf(py - ph * 0.5f, ay - ah * 0.5f);
    sx = fmaxf(sx, 0.f);
    sy = fmaxf(sy, 0.f);
    float inter = sx * sy;
    float uni = fmaf(pw, ph, fmaf(aw, ah, -inter));
    bool z = (uni == 0.f);
    n = z ? 0.f : inter;
    d = z ? EPS_F : uni;
}

__global__ __launch_bounds__(CPB, 10)
void yolo_loss_fused(const float* __restrict__ p,
                     const float* __restrict__ a,
                     float* __restrict__ out,
                     int ncells, int nblocks)
{
    __shared__ float sp[CPB * SMEM_STRIDE];
    __shared__ float sa[CPB * SMEM_STRIDE];

    const int tid = threadIdx.x;
    const int blockStart = blockIdx.x * CPB;
    const int nrec = min(CPB, ncells - blockStart);

    // ---- coalesced staging of channels 10..29 (10 float2 per record) ----
    const float2* p2 = reinterpret_cast<const float2*>(p);
    const float2* a2 = reinterpret_cast<const float2*>(a);
    const long gbase = (long)blockStart * 15;      // 120B record = 15 float2

    if (nrec == CPB) {
        // Fast path: compile-time trip count -> ptxas front-batches the
        // 20 independent LDG.64s for deep memory-level parallelism.
        #pragma unroll
        for (int k = 0; k < 10; k++) {
            int i = tid + k * CPB;                 // i in [0, 1280)
            int rec = i / 10;
            int j = i - rec * 10;
            long g = gbase + (long)rec * 15 + 5 + j;
            float2 vp = p2[g];
            float2 va = a2[g];
            int d = rec * SMEM_STRIDE + 2 * j;
            sp[d] = vp.x; sp[d + 1] = vp.y;
            sa[d] = va.x; sa[d + 1] = va.y;
        }
    } else {
        const int total = nrec * 10;
        for (int i = tid; i < total; i += CPB) {
            int rec = i / 10;
            int j = i - rec * 10;
            long g = gbase + (long)rec * 15 + 5 + j;
            float2 vp = p2[g];
            float2 va = a2[g];
            int d = rec * SMEM_STRIDE + 2 * j;
            sp[d] = vp.x; sp[d + 1] = vp.y;
            sa[d] = va.x; sa[d + 1] = va.y;
        }
    }
    __syncthreads();

    // ---- per-cell loss ----
    float loss = 0.f;
    if (tid < nrec) {
        const float* cp = &sp[tid * SMEM_STRIDE];  // k = channel-10, k in [0,20)
        const float* ca = &sa[tid * SMEM_STRIDE];

        float px[2], py[2], pw[2], ph[2], pc[2];
        float qx[2], qy[2], qw[2], qh[2], qc[2];
        #pragma unroll
        for (int b = 0; b < 2; b++) {
            int o = 10 + 5 * b;   // channels 20+5b.. -> k offset
            px[b] = cp[o]; py[b] = cp[o + 1]; pw[b] = cp[o + 2];
            ph[b] = cp[o + 3]; pc[b] = cp[o + 4];
            qx[b] = ca[o]; qy[b] = ca[o + 1]; qw[b] = ca[o + 2];
            qh[b] = ca[o + 3]; qc[b] = ca[o + 4];
        }

        // max_iou per predicted box as a fraction; argmax by cross-multiply
        float N[2], D[2];
        #pragma unroll
        for (int i = 0; i < 2; i++) {
            float n0, d0, n1, d1;
            iou_frac(px[i], py[i], pw[i], ph[i], qx[0], qy[0], qw[0], qh[0], n0, d0);
            iou_frac(px[i], py[i], pw[i], ph[i], qx[1], qy[1], qw[1], qh[1], n1, d1);
            bool take0 = (n0 * d1 >= n1 * d0);   // all d > 0
            N[i] = take0 ? n0 : n1;
            D[i] = take0 ? d0 : d1;
        }

        bool obj = qc[0] > 0.f;                    // a attr4 box0 (channel 24)
        bool resp0 = (N[0] * D[1] >= N[1] * D[0]); // argmax first-tie -> 0
        float ob[2];
        ob[0] = (obj && resp0)  ? 1.f : 0.f;
        ob[1] = (obj && !resp0) ? 1.f : 0.f;

        float coord = 0.f, cobj = 0.f, cnoobj = 0.f;
        #pragma unroll
        for (int b = 0; b < 2; b++) {
            float o = ob[b];
            float no = 1.f - o;
            float dx = o * qx[b] - o * px[b];
            float dy = o * qy[b] - o * py[b];
            coord += dx * dx + dy * dy;
            float dw = o * ssqrt(qw[b]) - o * ssqrt(pw[b]);
            float dh = o * ssqrt(qh[b]) - o * ssqrt(ph[b]);
            coord += dw * dw + dh * dh;
            float t1 = o * o - o * pc[b];
            cobj += t1 * t1;
            float t2 = no * o - no * pc[b];
            cnoobj += t2 * t2;
        }

        float cls = 0.f;
        if (obj) {
            #pragma unroll
            for (int k = 0; k < 20; k++) {
                float d = cp[k] - ca[k];
                cls += d * d;
            }
        }

        loss = 5.0f * coord + cobj + 0.5f * cnoobj + cls;
    }

    // ---- block reduction (4 warps) ----
    #pragma unroll
    for (int off = 16; off > 0; off >>= 1)
        loss += __shfl_down_sync(0xFFFFFFFFu, loss, off);

    __shared__ float warpsum[4];
    if ((tid & 31) == 0) warpsum[tid >> 5] = loss;
    __syncthreads();

    __shared__ bool s_last;
    if (tid == 0) {
        float v = warpsum[0] + warpsum[1] + warpsum[2] + warpsum[3];
        g_partials[blockIdx.x] = v;
        __threadfence();
        unsigned int t = atomicAdd(&g_ticket, 1u);
        s_last = (t == (unsigned int)(nblocks - 1));
    }
    __syncthreads();

    // ---- last block: deterministic final reduction + ticket reset ----
    if (s_last) {
        __threadfence();  // make all partials visible
        float s = 0.f;
        for (int i = tid; i < nblocks; i += CPB)
            s += g_partials[i];
        #pragma unroll
        for (int off = 16; off > 0; off >>= 1)
            s += __shfl_down_sync(0xFFFFFFFFu, s, off);
        if ((tid & 31) == 0) warpsum[tid >> 5] = s;
        __syncthreads();
        if (tid == 0) {
            out[0] = warpsum[0] + warpsum[1] + warpsum[2] + warpsum[3];
            g_ticket = 0;   // reset for next graph replay
        }
    }
}

extern "C" void kernel_launch(void* const* d_in, const int* in_sizes, int n_in,
                              void* d_out, int out_size)
{
    const float* p = (const float*)d_in[0];
    const float* a = (const float*)d_in[1];
    int ncells = in_sizes[0] / 30;                 // 16384*49 = 802816
    int nblocks = (ncells + CPB - 1) / CPB;        // 6272

    yolo_loss_fused<<<nblocks, CPB>>>(p, a, (float*)d_out, ncells, nblocks);
}